// round 15
// baseline (speedup 1.0000x reference)
#include <cuda_runtime.h>
#include <cuda_bf16.h>
#include <math.h>
#include <stdint.h>

#define NN 4096
#define DD 256

// ---------------- device scratch (no allocations allowed) ----------------
__device__ float d_key[NN];
__device__ float d_nrmR[NN];
__device__ float d_nrmM[NN];
__device__ int   d_rank[NN];
__device__ int   d_sidx[NN];
__device__ float d_Gs[(size_t)NN * NN];          // G in sorted coords
__device__ __nv_bfloat16 d_Rhi[(size_t)NN * DD];
__device__ __nv_bfloat16 d_Rlo[(size_t)NN * DD];
__device__ __nv_bfloat16 d_Mhi[(size_t)NN * DD];
__device__ __nv_bfloat16 d_Mlo[(size_t)NN * DD];

// ---------------- K1: merged prologue -------------------------------------
// blocks [0,NN): sort key (BIT-EXACT reduction — do not touch) + uR norms
//                + uR hi/lo split + rank zeroing
// blocks [NN,2NN): uM norms + uM hi/lo split
__global__ void k_pre(const float* __restrict__ uR, const float* __restrict__ uM) {
    int blk = blockIdx.x;
    int t = threadIdx.x;
    int w = t >> 5, lane = t & 31;

    if (blk < NN) {
        int row = blk;
        int gi = row * DD + t;
        float x = uR[gi];

        __nv_bfloat16 h = __float2bfloat16(x);
        d_Rhi[gi] = h;
        d_Rlo[gi] = __float2bfloat16(x - __bfloat162float(h));
        if (t == 0) d_rank[row] = 0;

        float q = __fdiv_rn(x, 1.41421356237309515f);
        float p = __fadd_rn(0.5f, __fmul_rn(0.5f, erff(q)));
        float v = logf(p);
        float n = x * x;
#pragma unroll
        for (int off = 16; off > 0; off >>= 1) {
            v = __fadd_rn(v, __shfl_down_sync(0xffffffffu, v, off));
            n += __shfl_down_sync(0xffffffffu, n, off);
        }
        __shared__ float wp[8], wn[8];
        if (lane == 0) { wp[w] = v; wn[w] = n; }
        __syncthreads();
        if (w == 0) {
            float pv = (lane < 8) ? wp[lane] : 0.0f;
            float pn = (lane < 8) ? wn[lane] : 0.0f;
#pragma unroll
            for (int off = 16; off > 0; off >>= 1) {
                pv = __fadd_rn(pv, __shfl_down_sync(0xffffffffu, pv, off));
                pn += __shfl_down_sync(0xffffffffu, pn, off);
            }
            if (lane == 0) { d_key[row] = pv; d_nrmR[row] = pn; }
        }
    } else {
        int row = blk - NN;
        int gi = row * DD + t;
        float x = uM[gi];
        __nv_bfloat16 h = __float2bfloat16(x);
        d_Mhi[gi] = h;
        d_Mlo[gi] = __float2bfloat16(x - __bfloat162float(h));

        float n = x * x;
#pragma unroll
        for (int off = 16; off > 0; off >>= 1) n += __shfl_down_sync(0xffffffffu, n, off);
        __shared__ float wn2[8];
        if (lane == 0) wn2[w] = n;
        __syncthreads();
        if (w == 0) {
            float pn = (lane < 8) ? wn2[lane] : 0.0f;
#pragma unroll
            for (int off = 16; off > 0; off >>= 1) pn += __shfl_down_sync(0xffffffffu, pn, off);
            if (lane == 0) d_nrmM[row] = pn;
        }
    }
}

// ---------------- K2: parallel stable ranks (partial counts + atomics) ----
__global__ void k_rankp() {
    __shared__ float keys[256];
    int tid = threadIdx.x;
    int j0 = blockIdx.y * 256;
    keys[tid] = d_key[j0 + tid];
    __syncthreads();
    int i = blockIdx.x * 256 + tid;
    float ki = d_key[i];
    int cnt = 0;
#pragma unroll 8
    for (int jj = 0; jj < 256; jj++) {
        float kj = keys[jj];
        int j = j0 + jj;
        cnt += (kj < ki) || (kj == ki && j < i);
    }
    atomicAdd(&d_rank[i], cnt);
}

__global__ void k_sidx() {
    int i = blockIdx.x * 256 + threadIdx.x;
    d_sidx[d_rank[i]] = i;
}

// ---------------- packed f32x2 epilogue math (PINNED — do not modify) -----
typedef unsigned long long ull;
__device__ __forceinline__ ull pk2(float x, float y) {
    ull r; asm("mov.b64 %0, {%1, %2};" : "=l"(r) : "f"(x), "f"(y)); return r;
}
__device__ __forceinline__ void upk2(ull v, float& x, float& y) {
    asm("mov.b64 {%0, %1}, %2;" : "=f"(x), "=f"(y) : "l"(v));
}
__device__ __forceinline__ ull fma2(ull a, ull b, ull c) {
    ull d; asm("fma.rn.f32x2 %0, %1, %2, %3;" : "=l"(d) : "l"(a), "l"(b), "l"(c)); return d;
}
__device__ __forceinline__ ull mul2(ull a, ull b) {
    ull d; asm("mul.rn.f32x2 %0, %1, %2;" : "=l"(d) : "l"(a), "l"(b)); return d;
}
__device__ __forceinline__ ull add2(ull a, ull b) {
    ull d; asm("add.rn.f32x2 %0, %1, %2;" : "=l"(d) : "l"(a), "l"(b)); return d;
}

// packed exp2; valid for t in (-126, 126); round via +1.5*2^23 magic-add
__device__ __forceinline__ ull exp2x2(ull t2) {
    ull m2  = add2(t2, pk2(12582912.0f, 12582912.0f));
    ull fk2 = add2(m2, pk2(-12582912.0f, -12582912.0f));
    ull f2  = fma2(fk2, pk2(-1.0f, -1.0f), t2);          // f = t - rint(t)
    ull p2  = pk2(1.3333558146e-3f, 1.3333558146e-3f);
    p2 = fma2(p2, f2, pk2(9.6181291076e-3f, 9.6181291076e-3f));
    p2 = fma2(p2, f2, pk2(5.5504108664e-2f, 5.5504108664e-2f));
    p2 = fma2(p2, f2, pk2(2.4022650696e-1f, 2.4022650696e-1f));
    p2 = fma2(p2, f2, pk2(6.9314718056e-1f, 6.9314718056e-1f));
    p2 = fma2(p2, f2, pk2(1.0f, 1.0f));
    float mx, my; upk2(m2, mx, my);
    float sx = __int_as_float((__float_as_int(mx) + 127) << 23);  // 2^k
    float sy = __int_as_float((__float_as_int(my) + 127) << 23);
    return mul2(p2, pk2(sx, sy));
}

// two elements: sigmoid((logitexp(logp)+log(u/(1-u)))/0.3), logp <= -0.7
__device__ __forceinline__ float2 epi2(float acx, float acy, float na,
                                       float nb0, float nb1, float nhs,
                                       float ux, float uy) {
    float d2x = fmaxf(fmaf(-2.0f, acx, na + nb0), 0.0f);
    float d2y = fmaxf(fmaf(-2.0f, acy, na + nb1), 0.0f);
    ull logp2 = mul2(pk2(d2x, d2y), pk2(nhs, nhs));
    ull p2 = exp2x2(mul2(logp2, pk2(1.4426950409f, 1.4426950409f)));
    ull L2 = add2(logp2, p2);              // logp - log(1-p) ~= logp + p
    ux = fminf(fmaxf(ux, 1e-6f), 1.0f - 1e-6f);
    uy = fminf(fmaxf(uy, 1e-6f), 1.0f - 1e-6f);
    float Sx = __logf(ux) - __logf(1.0f - ux);            // MUFU pipe
    float Sy = __logf(uy) - __logf(1.0f - uy);
    ull t2 = mul2(add2(L2, pk2(Sx, Sy)), pk2(-4.8089834697f, -4.8089834697f));
    float tx, ty; upk2(t2, tx, ty);
    tx = fminf(tx, 126.0f); ty = fminf(ty, 126.0f);
    ull w2 = exp2x2(pk2(tx, ty));
    ull xd2 = add2(w2, pk2(1.0f, 1.0f));
    float xx, xy; upk2(xd2, xx, xy);
    float2 o;
    o.x = __fdividef(1.0f, xx);                           // MUFU rcp
    o.y = __fdividef(1.0f, xy);
    return o;
}

// ---------------- merged fused HMMA GEMM + packed epilogue ----------------
// Single launch: blocks [0,528) = G upper-triangle tiles (sorted coords),
// blocks [528,1552) = A tiles. CTA tile 128x128, 8 warps, BK=32.
// FUSED-TERM stages: each 32KB stage holds Ahi,Alo,Bhi,Blo for one k-chunk.
// Mainloop FULLY UNROLLED: stage indices are compile-time constants.
// U tile cp.async'd into the stage slots that die in the last two iterations.
#define STAGE_T 32768
#define SMEM_DYN (3 * STAGE_T)

__device__ __forceinline__ void ldsm_x4(uint32_t* r, uint32_t addr) {
    asm volatile("ldmatrix.sync.aligned.m8n8.x4.shared.b16 {%0,%1,%2,%3}, [%4];"
                 : "=r"(r[0]), "=r"(r[1]), "=r"(r[2]), "=r"(r[3]) : "r"(addr));
}
__device__ __forceinline__ void mma16816(float* d, const uint32_t* a,
                                         uint32_t b0, uint32_t b1) {
    asm volatile(
        "mma.sync.aligned.m16n8k16.row.col.f32.bf16.bf16.f32 "
        "{%0,%1,%2,%3}, {%4,%5,%6,%7}, {%8,%9}, {%0,%1,%2,%3};"
        : "+f"(d[0]), "+f"(d[1]), "+f"(d[2]), "+f"(d[3])
        : "r"(a[0]), "r"(a[1]), "r"(a[2]), "r"(a[3]), "r"(b0), "r"(b1));
}
__device__ __forceinline__ uint32_t smem_u32(const void* p) {
    uint32_t a;
    asm("{ .reg .u64 t; cvta.to.shared.u64 t, %1; cvt.u32.u64 %0, t; }" : "=r"(a) : "l"(p));
    return a;
}
__device__ __forceinline__ float2 lds64(uint32_t a) {
    float2 v;
    asm volatile("ld.shared.v2.f32 {%0,%1}, [%2];" : "=f"(v.x), "=f"(v.y) : "r"(a));
    return v;
}

__global__ void __launch_bounds__(256, 2)
k_gemm(const __nv_bfloat16* __restrict__ Rhi, const __nv_bfloat16* __restrict__ Rlo,
       const __nv_bfloat16* __restrict__ Mhi, const __nv_bfloat16* __restrict__ Mlo,
       const float* __restrict__ uG, const float* __restrict__ uA,
       const float* __restrict__ gls,
       float* __restrict__ Gs, float* __restrict__ OutA)
{
    extern __shared__ __align__(128) char dsm[];
    __shared__ int   shA[128], shB[128];
    __shared__ float snA[128], snB[128];

    const int tid = threadIdx.x;
    const int wid = tid >> 5;
    const int lane = tid & 31;
    const int warp_m = wid & 1;
    const int warp_n = wid >> 1;

    const bool tri = blockIdx.x < 528;
    int ta, tb;
    if (tri) {
        int rem = blockIdx.x; ta = 0;
        while (rem >= (32 - ta)) { rem -= (32 - ta); ta++; }
        tb = ta + rem;
    } else { int r = blockIdx.x - 528; ta = r >> 5; tb = r & 31; }
    const int a0 = ta * 128, b0 = tb * 128;

    const __nv_bfloat16* Ahi = tri ? Rhi : Mhi;
    const __nv_bfloat16* Alo = tri ? Rlo : Mlo;
    const float* U = tri ? uG : uA;
    float* Out = tri ? Gs : OutA;

    if (tid < 128) {
        int a = a0 + tid;
        int ra = tri ? d_sidx[a] : a;
        shA[tid] = ra;
        snA[tid] = tri ? d_nrmR[ra] : d_nrmM[ra];
    } else {
        int b = b0 + tid - 128;
        int rb = tri ? d_sidx[b] : b;
        shB[tid - 128] = rb;
        snB[tid - 128] = d_nrmR[rb];
    }
    __syncthreads();

    uint32_t smBase = smem_u32(dsm);

    // stage slots: [Ahi 8K][Alo 8K][Bhi 8K][Blo 8K]
    auto load_stage = [&](int ks, int s) {
        int k0 = ks * 32;
        uint32_t sAh = smBase + s * STAGE_T;
#pragma unroll
        for (int j = 0; j < 2; j++) {
            int idx = tid + j * 256;          // 0..511
            int m = idx >> 2, kc = idx & 3;
            uint32_t off = (uint32_t)(((m >> 3) * 4 + kc) * 128 + (m & 7) * 16);
            size_t goA = (size_t)shA[m] * DD + k0 + kc * 8;
            size_t goB = (size_t)shB[m] * DD + k0 + kc * 8;
            asm volatile("cp.async.cg.shared.global [%0], [%1], 16;"
                         :: "r"(sAh + off), "l"((const void*)(Ahi + goA)));
            asm volatile("cp.async.cg.shared.global [%0], [%1], 16;"
                         :: "r"(sAh + 8192 + off), "l"((const void*)(Alo + goA)));
            asm volatile("cp.async.cg.shared.global [%0], [%1], 16;"
                         :: "r"(sAh + 16384 + off), "l"((const void*)(Rhi + goB)));
            asm volatile("cp.async.cg.shared.global [%0], [%1], 16;"
                         :: "r"(sAh + 24576 + off), "l"((const void*)(Rlo + goB)));
        }
        asm volatile("cp.async.commit_group;");
    };

    // U prefetch: half 0 (rows 0-63) -> slot 2; half 1 (rows 64-127) -> slot 0.
    // 16B chunks XOR-swizzled by (row&7) for conflict-free epilogue LDS.64.
    auto load_u = [&](int half) {
        uint32_t uB = half ? smBase : (smBase + 2 * STAGE_T);
#pragma unroll
        for (int q = 0; q < 8; q++) {
            int idx = tid + q * 256;          // 0..2047
            int row = idx >> 5;               // 0..63
            int c16 = idx & 31;
            int ch = c16 ^ (row & 7);
            const void* g = U + (size_t)(a0 + half * 64 + row) * NN + b0 + c16 * 4;
            asm volatile("cp.async.cg.shared.global [%0], [%1], 16;"
                         :: "r"(uB + (uint32_t)(row * 512 + ch * 16)), "l"(g));
        }
        asm volatile("cp.async.commit_group;");
    };

    float acc[4][4][4];
#pragma unroll
    for (int i = 0; i < 4; i++)
#pragma unroll
        for (int j = 0; j < 4; j++)
#pragma unroll
            for (int q = 0; q < 4; q++) acc[i][j][q] = 0.0f;

    const int mat = lane >> 3, ri = lane & 7;
    const uint32_t cA = (uint32_t)((mat & 1) * 512 + (mat >> 1) * 128 + ri * 16);
    const uint32_t cB = (uint32_t)((mat >> 1) * 512 + (mat & 1) * 128 + ri * 16);

    const int NK = 8;
    load_stage(0, 0);
    load_stage(1, 1);
#pragma unroll
    for (int ks = 0; ks < NK; ks++) {
        const int s = ks % 3;                 // compile-time after unroll
        asm volatile("cp.async.wait_group 1;");
        __syncthreads();
        if (ks + 2 < NK) {
            load_stage(ks + 2, (ks + 2) % 3); // slot free since iter ks-1
        } else {
            load_u(ks - (NK - 2));            // ks==6: half0 -> slot2; ks==7: half1 -> slot0
        }

        uint32_t aHi = smBase + s * STAGE_T + warp_m * 4096 + cA;
        uint32_t bHi = smBase + s * STAGE_T + 16384 + warp_n * 2048 + cB;
#pragma unroll
        for (int kh = 0; kh < 2; kh++) {
            uint32_t ah[4][4], al[4][4], bh[2][4], bl[2][4];
            // all fragment loads up-front; latency hidden by 96 mma below
#pragma unroll
            for (int mt = 0; mt < 4; mt++)
                ldsm_x4(ah[mt], aHi + mt * 1024 + kh * 256);
#pragma unroll
            for (int h = 0; h < 2; h++) {
                ldsm_x4(bh[h], bHi + h * 1024 + kh * 256);
                ldsm_x4(bl[h], bHi + 8192 + h * 1024 + kh * 256);
            }
#pragma unroll
            for (int mt = 0; mt < 4; mt++)
                ldsm_x4(al[mt], aHi + 8192 + mt * 1024 + kh * 256);
            // term 1: hi*hi
#pragma unroll
            for (int mt = 0; mt < 4; mt++)
#pragma unroll
                for (int h = 0; h < 2; h++) {
                    mma16816(acc[mt][2 * h],     ah[mt], bh[h][0], bh[h][1]);
                    mma16816(acc[mt][2 * h + 1], ah[mt], bh[h][2], bh[h][3]);
                }
            // term 2: hi*lo
#pragma unroll
            for (int mt = 0; mt < 4; mt++)
#pragma unroll
                for (int h = 0; h < 2; h++) {
                    mma16816(acc[mt][2 * h],     ah[mt], bl[h][0], bl[h][1]);
                    mma16816(acc[mt][2 * h + 1], ah[mt], bl[h][2], bl[h][3]);
                }
            // term 3: lo*hi
#pragma unroll
            for (int mt = 0; mt < 4; mt++)
#pragma unroll
                for (int h = 0; h < 2; h++) {
                    mma16816(acc[mt][2 * h],     al[mt], bh[h][0], bh[h][1]);
                    mma16816(acc[mt][2 * h + 1], al[mt], bh[h][2], bh[h][3]);
                }
        }
    }

    // drain U halves, make smem writes visible to all warps
    asm volatile("cp.async.wait_group 0;");
    __syncthreads();

    // ---- epilogue: packed f32x2 math, U from smem, coalesced v2 stores ----
    float scale = expf(gls[0]);
    float nhs = -0.5f / scale;
    const int rl = lane >> 2, cl = (lane & 3) * 2;
    const uint32_t uB = warp_m ? smBase : (smBase + 2 * STAGE_T);

#pragma unroll
    for (int mt = 0; mt < 4; mt++) {
        int lr = warp_m * 64 + mt * 16 + rl;
        int rloc = mt * 16 + rl;              // local row within half (0..63)
        float na0 = snA[lr], na1 = snA[lr + 8];
        size_t g0 = (size_t)(a0 + lr) * NN + b0;
        size_t g1 = g0 + (size_t)8 * NN;
#pragma unroll
        for (int ng = 0; ng < 4; ng++) {
            int cc = warp_n * 32 + ng * 8 + cl;
            float nb0 = snB[cc], nb1 = snB[cc + 1];
            uint32_t uoff = (uint32_t)((((cc >> 2) ^ rl) << 4) + ((cc & 3) << 2));
            float2 u0 = lds64(uB + rloc * 512 + uoff);
            float2 u1 = lds64(uB + (rloc + 8) * 512 + uoff);
            const float* ac = acc[mt][ng];
            float2 o0 = epi2(ac[0], ac[1], na0, nb0, nb1, nhs, u0.x, u0.y);
            float2 o1 = epi2(ac[2], ac[3], na1, nb0, nb1, nhs, u1.x, u1.y);
            *(float2*)&Out[g0 + cc] = o0;      // lower-tri garbage in tri tiles
            *(float2*)&Out[g1 + cc] = o1;      // is never read by k_permG
        }
    }
}

// ---------------- K4: permute G back (float4, half-row read) -------------
__global__ void k_permG(float* __restrict__ out0) {
    __shared__ float rowbuf[NN];
    int i = blockIdx.x;
    int a = d_rank[i];
    const float4* src = (const float4*)(d_Gs + (size_t)a * NN);
    // only columns > a of sorted row a are ever read (rj > a below)
    int j4start = a >> 2;
    for (int j = j4start + threadIdx.x; j < NN / 4; j += blockDim.x)
        ((float4*)rowbuf)[j] = src[j];
    __syncthreads();
    float4* dst = (float4*)(out0 + (size_t)i * NN);
    const int4* rk = (const int4*)d_rank;
    for (int j4 = threadIdx.x; j4 < NN / 4; j4 += blockDim.x) {
        int4 rj = rk[j4];
        float4 v;
        v.x = (rj.x > a) ? rowbuf[rj.x] : 0.0f;
        v.y = (rj.y > a) ? rowbuf[rj.y] : 0.0f;
        v.z = (rj.z > a) ? rowbuf[rj.z] : 0.0f;
        v.w = (rj.w > a) ? rowbuf[rj.w] : 0.0f;
        dst[j4] = v;
    }
}

// ---------------- launch ---------------------------------------------------
extern "C" void kernel_launch(void* const* d_in, const int* in_sizes, int n_in,
                              void* d_out, int out_size) {
    (void)in_sizes; (void)n_in; (void)out_size;
    const float* uR  = (const float*)d_in[0];
    const float* uM  = (const float*)d_in[1];
    const float* gls = (const float*)d_in[2];
    const float* uG  = (const float*)d_in[3];
    const float* uA  = (const float*)d_in[4];
    float* out = (float*)d_out;

    // opt-in for 96KB dynamic smem (host-side, capture-legal, idempotent)
    cudaFuncSetAttribute(k_gemm, cudaFuncAttributeMaxDynamicSharedMemorySize, SMEM_DYN);

    k_pre<<<2 * NN, 256>>>(uR, uM);   // keys + norms + bf16 splits + rank zeroing
    {
        dim3 g(16, 16);
        k_rankp<<<g, 256>>>();        // parallel partial rank counts
    }
    k_sidx<<<16, 256>>>();

    __nv_bfloat16 *Rhi, *Rlo, *Mhi, *Mlo;
    cudaGetSymbolAddress((void**)&Rhi, d_Rhi);
    cudaGetSymbolAddress((void**)&Rlo, d_Rlo);
    cudaGetSymbolAddress((void**)&Mhi, d_Mhi);
    cudaGetSymbolAddress((void**)&Mlo, d_Mlo);
    float* Gs;
    cudaGetSymbolAddress((void**)&Gs, d_Gs);

    // merged G (528 triangle tiles) + A (1024 tiles) in one launch
    k_gemm<<<1552, 256, SMEM_DYN>>>(Rhi, Rlo, Mhi, Mlo, uG, uA, gls,
                                    Gs, out + (size_t)NN * NN);
    k_permG<<<NN, 512>>>(out);
}

// round 16
// speedup vs baseline: 1.5277x; 1.5277x over previous
#include <cuda_runtime.h>
#include <cuda_bf16.h>
#include <math.h>
#include <stdint.h>

#define NN 4096
#define DD 256

// ---------------- device scratch (no allocations allowed) ----------------
__device__ float d_key[NN];
__device__ float d_nrmR[NN];
__device__ float d_nrmM[NN];
__device__ int   d_rank[NN];
__device__ int   d_sidx[NN];
__device__ float d_Gs[(size_t)NN * NN];          // G in sorted coords
__device__ __nv_bfloat16 d_Rhi[(size_t)NN * DD];
__device__ __nv_bfloat16 d_Rlo[(size_t)NN * DD];
__device__ __nv_bfloat16 d_Mhi[(size_t)NN * DD];
__device__ __nv_bfloat16 d_Mlo[(size_t)NN * DD];

// ---------------- K1: merged prologue -------------------------------------
// blocks [0,NN): sort key (BIT-EXACT reduction — do not touch) + uR norms
//                + uR hi/lo split + rank zeroing
// blocks [NN,2NN): uM norms + uM hi/lo split
__global__ void k_pre(const float* __restrict__ uR, const float* __restrict__ uM) {
    int blk = blockIdx.x;
    int t = threadIdx.x;
    int w = t >> 5, lane = t & 31;

    if (blk < NN) {
        int row = blk;
        int gi = row * DD + t;
        float x = uR[gi];

        __nv_bfloat16 h = __float2bfloat16(x);
        d_Rhi[gi] = h;
        d_Rlo[gi] = __float2bfloat16(x - __bfloat162float(h));
        if (t == 0) d_rank[row] = 0;

        float q = __fdiv_rn(x, 1.41421356237309515f);
        float p = __fadd_rn(0.5f, __fmul_rn(0.5f, erff(q)));
        float v = logf(p);
        float n = x * x;
#pragma unroll
        for (int off = 16; off > 0; off >>= 1) {
            v = __fadd_rn(v, __shfl_down_sync(0xffffffffu, v, off));
            n += __shfl_down_sync(0xffffffffu, n, off);
        }
        __shared__ float wp[8], wn[8];
        if (lane == 0) { wp[w] = v; wn[w] = n; }
        __syncthreads();
        if (w == 0) {
            float pv = (lane < 8) ? wp[lane] : 0.0f;
            float pn = (lane < 8) ? wn[lane] : 0.0f;
#pragma unroll
            for (int off = 16; off > 0; off >>= 1) {
                pv = __fadd_rn(pv, __shfl_down_sync(0xffffffffu, pv, off));
                pn += __shfl_down_sync(0xffffffffu, pn, off);
            }
            if (lane == 0) { d_key[row] = pv; d_nrmR[row] = pn; }
        }
    } else {
        int row = blk - NN;
        int gi = row * DD + t;
        float x = uM[gi];
        __nv_bfloat16 h = __float2bfloat16(x);
        d_Mhi[gi] = h;
        d_Mlo[gi] = __float2bfloat16(x - __bfloat162float(h));

        float n = x * x;
#pragma unroll
        for (int off = 16; off > 0; off >>= 1) n += __shfl_down_sync(0xffffffffu, n, off);
        __shared__ float wn2[8];
        if (lane == 0) wn2[w] = n;
        __syncthreads();
        if (w == 0) {
            float pn = (lane < 8) ? wn2[lane] : 0.0f;
#pragma unroll
            for (int off = 16; off > 0; off >>= 1) pn += __shfl_down_sync(0xffffffffu, pn, off);
            if (lane == 0) d_nrmM[row] = pn;
        }
    }
}

// ---------------- K2: parallel stable ranks (partial counts + atomics) ----
__global__ void k_rankp() {
    __shared__ float keys[256];
    int tid = threadIdx.x;
    int j0 = blockIdx.y * 256;
    keys[tid] = d_key[j0 + tid];
    __syncthreads();
    int i = blockIdx.x * 256 + tid;
    float ki = d_key[i];
    int cnt = 0;
#pragma unroll 8
    for (int jj = 0; jj < 256; jj++) {
        float kj = keys[jj];
        int j = j0 + jj;
        cnt += (kj < ki) || (kj == ki && j < i);
    }
    atomicAdd(&d_rank[i], cnt);
}

__global__ void k_sidx() {
    int i = blockIdx.x * 256 + threadIdx.x;
    d_sidx[d_rank[i]] = i;
}

// ---------------- packed f32x2 epilogue math (PINNED — do not modify) -----
typedef unsigned long long ull;
__device__ __forceinline__ ull pk2(float x, float y) {
    ull r; asm("mov.b64 %0, {%1, %2};" : "=l"(r) : "f"(x), "f"(y)); return r;
}
__device__ __forceinline__ void upk2(ull v, float& x, float& y) {
    asm("mov.b64 {%0, %1}, %2;" : "=f"(x), "=f"(y) : "l"(v));
}
__device__ __forceinline__ ull fma2(ull a, ull b, ull c) {
    ull d; asm("fma.rn.f32x2 %0, %1, %2, %3;" : "=l"(d) : "l"(a), "l"(b), "l"(c)); return d;
}
__device__ __forceinline__ ull mul2(ull a, ull b) {
    ull d; asm("mul.rn.f32x2 %0, %1, %2;" : "=l"(d) : "l"(a), "l"(b)); return d;
}
__device__ __forceinline__ ull add2(ull a, ull b) {
    ull d; asm("add.rn.f32x2 %0, %1, %2;" : "=l"(d) : "l"(a), "l"(b)); return d;
}

// packed exp2; valid for t in (-126, 126); round via +1.5*2^23 magic-add
__device__ __forceinline__ ull exp2x2(ull t2) {
    ull m2  = add2(t2, pk2(12582912.0f, 12582912.0f));
    ull fk2 = add2(m2, pk2(-12582912.0f, -12582912.0f));
    ull f2  = fma2(fk2, pk2(-1.0f, -1.0f), t2);          // f = t - rint(t)
    ull p2  = pk2(1.3333558146e-3f, 1.3333558146e-3f);
    p2 = fma2(p2, f2, pk2(9.6181291076e-3f, 9.6181291076e-3f));
    p2 = fma2(p2, f2, pk2(5.5504108664e-2f, 5.5504108664e-2f));
    p2 = fma2(p2, f2, pk2(2.4022650696e-1f, 2.4022650696e-1f));
    p2 = fma2(p2, f2, pk2(6.9314718056e-1f, 6.9314718056e-1f));
    p2 = fma2(p2, f2, pk2(1.0f, 1.0f));
    float mx, my; upk2(m2, mx, my);
    float sx = __int_as_float((__float_as_int(mx) + 127) << 23);  // 2^k
    float sy = __int_as_float((__float_as_int(my) + 127) << 23);
    return mul2(p2, pk2(sx, sy));
}

// two elements: sigmoid((logitexp(logp)+log(u/(1-u)))/0.3), logp <= -0.7
__device__ __forceinline__ float2 epi2(float acx, float acy, float na,
                                       float nb0, float nb1, float nhs,
                                       float ux, float uy) {
    float d2x = fmaxf(fmaf(-2.0f, acx, na + nb0), 0.0f);
    float d2y = fmaxf(fmaf(-2.0f, acy, na + nb1), 0.0f);
    ull logp2 = mul2(pk2(d2x, d2y), pk2(nhs, nhs));
    ull p2 = exp2x2(mul2(logp2, pk2(1.4426950409f, 1.4426950409f)));
    ull L2 = add2(logp2, p2);              // logp - log(1-p) ~= logp + p
    ux = fminf(fmaxf(ux, 1e-6f), 1.0f - 1e-6f);
    uy = fminf(fmaxf(uy, 1e-6f), 1.0f - 1e-6f);
    float Sx = __logf(ux) - __logf(1.0f - ux);            // MUFU pipe
    float Sy = __logf(uy) - __logf(1.0f - uy);
    ull t2 = mul2(add2(L2, pk2(Sx, Sy)), pk2(-4.8089834697f, -4.8089834697f));
    float tx, ty; upk2(t2, tx, ty);
    tx = fminf(tx, 126.0f); ty = fminf(ty, 126.0f);
    ull w2 = exp2x2(pk2(tx, ty));
    ull xd2 = add2(w2, pk2(1.0f, 1.0f));
    float xx, xy; upk2(xd2, xx, xy);
    float2 o;
    o.x = __fdividef(1.0f, xx);                           // MUFU rcp
    o.y = __fdividef(1.0f, xy);
    return o;
}

// ---------------- merged fused HMMA GEMM + packed epilogue ----------------
// Single launch: blocks [0,528) = G upper-triangle tiles (sorted coords),
// blocks [528,1552) = A tiles. CTA tile 128x128, 8 warps, BK=32.
// FUSED-TERM stages: each 32KB stage holds Ahi,Alo,Bhi,Blo for one k-chunk.
// Mainloop FULLY UNROLLED: stage indices are compile-time constants.
// U tile cp.async'd into the stage slots that die in the last two iterations.
#define STAGE_T 32768
#define SMEM_DYN (3 * STAGE_T)

__device__ __forceinline__ void ldsm_x4(uint32_t* r, uint32_t addr) {
    asm volatile("ldmatrix.sync.aligned.m8n8.x4.shared.b16 {%0,%1,%2,%3}, [%4];"
                 : "=r"(r[0]), "=r"(r[1]), "=r"(r[2]), "=r"(r[3]) : "r"(addr));
}
__device__ __forceinline__ void mma16816(float* d, const uint32_t* a,
                                         uint32_t b0, uint32_t b1) {
    asm volatile(
        "mma.sync.aligned.m16n8k16.row.col.f32.bf16.bf16.f32 "
        "{%0,%1,%2,%3}, {%4,%5,%6,%7}, {%8,%9}, {%0,%1,%2,%3};"
        : "+f"(d[0]), "+f"(d[1]), "+f"(d[2]), "+f"(d[3])
        : "r"(a[0]), "r"(a[1]), "r"(a[2]), "r"(a[3]), "r"(b0), "r"(b1));
}
__device__ __forceinline__ uint32_t smem_u32(const void* p) {
    uint32_t a;
    asm("{ .reg .u64 t; cvta.to.shared.u64 t, %1; cvt.u32.u64 %0, t; }" : "=r"(a) : "l"(p));
    return a;
}
__device__ __forceinline__ float2 lds64(uint32_t a) {
    float2 v;
    asm volatile("ld.shared.v2.f32 {%0,%1}, [%2];" : "=f"(v.x), "=f"(v.y) : "r"(a));
    return v;
}

__global__ void __launch_bounds__(256, 2)
k_gemm(const __nv_bfloat16* __restrict__ Rhi, const __nv_bfloat16* __restrict__ Rlo,
       const __nv_bfloat16* __restrict__ Mhi, const __nv_bfloat16* __restrict__ Mlo,
       const float* __restrict__ uG, const float* __restrict__ uA,
       const float* __restrict__ gls,
       float* __restrict__ Gs, float* __restrict__ OutA)
{
    extern __shared__ __align__(128) char dsm[];
    __shared__ int   shA[128], shB[128];
    __shared__ float snA[128], snB[128];

    const int tid = threadIdx.x;
    const int wid = tid >> 5;
    const int lane = tid & 31;
    const int warp_m = wid & 1;
    const int warp_n = wid >> 1;

    const bool tri = blockIdx.x < 528;
    int ta, tb;
    if (tri) {
        int rem = blockIdx.x; ta = 0;
        while (rem >= (32 - ta)) { rem -= (32 - ta); ta++; }
        tb = ta + rem;
    } else { int r = blockIdx.x - 528; ta = r >> 5; tb = r & 31; }
    const int a0 = ta * 128, b0 = tb * 128;

    const __nv_bfloat16* Ahi = tri ? Rhi : Mhi;
    const __nv_bfloat16* Alo = tri ? Rlo : Mlo;
    const float* U = tri ? uG : uA;
    float* Out = tri ? Gs : OutA;

    if (tid < 128) {
        int a = a0 + tid;
        int ra = tri ? d_sidx[a] : a;
        shA[tid] = ra;
        snA[tid] = tri ? d_nrmR[ra] : d_nrmM[ra];
    } else {
        int b = b0 + tid - 128;
        int rb = tri ? d_sidx[b] : b;
        shB[tid - 128] = rb;
        snB[tid - 128] = d_nrmR[rb];
    }
    __syncthreads();

    uint32_t smBase = smem_u32(dsm);

    // stage slots: [Ahi 8K][Alo 8K][Bhi 8K][Blo 8K]
    auto load_stage = [&](int ks, int s) {
        int k0 = ks * 32;
        uint32_t sAh = smBase + s * STAGE_T;
#pragma unroll
        for (int j = 0; j < 2; j++) {
            int idx = tid + j * 256;          // 0..511
            int m = idx >> 2, kc = idx & 3;
            uint32_t off = (uint32_t)(((m >> 3) * 4 + kc) * 128 + (m & 7) * 16);
            size_t goA = (size_t)shA[m] * DD + k0 + kc * 8;
            size_t goB = (size_t)shB[m] * DD + k0 + kc * 8;
            asm volatile("cp.async.cg.shared.global [%0], [%1], 16;"
                         :: "r"(sAh + off), "l"((const void*)(Ahi + goA)));
            asm volatile("cp.async.cg.shared.global [%0], [%1], 16;"
                         :: "r"(sAh + 8192 + off), "l"((const void*)(Alo + goA)));
            asm volatile("cp.async.cg.shared.global [%0], [%1], 16;"
                         :: "r"(sAh + 16384 + off), "l"((const void*)(Rhi + goB)));
            asm volatile("cp.async.cg.shared.global [%0], [%1], 16;"
                         :: "r"(sAh + 24576 + off), "l"((const void*)(Rlo + goB)));
        }
        asm volatile("cp.async.commit_group;");
    };

    // U prefetch: half 0 (rows 0-63) -> slot 2; half 1 (rows 64-127) -> slot 0.
    // 16B chunks XOR-swizzled by (row&7) for conflict-free epilogue LDS.64.
    auto load_u = [&](int half) {
        uint32_t uB = half ? smBase : (smBase + 2 * STAGE_T);
#pragma unroll
        for (int q = 0; q < 8; q++) {
            int idx = tid + q * 256;          // 0..2047
            int row = idx >> 5;               // 0..63
            int c16 = idx & 31;
            int ch = c16 ^ (row & 7);
            const void* g = U + (size_t)(a0 + half * 64 + row) * NN + b0 + c16 * 4;
            asm volatile("cp.async.cg.shared.global [%0], [%1], 16;"
                         :: "r"(uB + (uint32_t)(row * 512 + ch * 16)), "l"(g));
        }
        asm volatile("cp.async.commit_group;");
    };

    float acc[4][4][4];
#pragma unroll
    for (int i = 0; i < 4; i++)
#pragma unroll
        for (int j = 0; j < 4; j++)
#pragma unroll
            for (int q = 0; q < 4; q++) acc[i][j][q] = 0.0f;

    const int mat = lane >> 3, ri = lane & 7;
    const uint32_t cA = (uint32_t)((mat & 1) * 512 + (mat >> 1) * 128 + ri * 16);
    const uint32_t cB = (uint32_t)((mat >> 1) * 512 + (mat & 1) * 128 + ri * 16);

    const int NK = 8;
    load_stage(0, 0);
    load_stage(1, 1);
#pragma unroll
    for (int ks = 0; ks < NK; ks++) {
        const int s = ks % 3;                 // compile-time after unroll
        asm volatile("cp.async.wait_group 1;");
        __syncthreads();
        if (ks + 2 < NK) {
            load_stage(ks + 2, (ks + 2) % 3); // slot free since iter ks-1
        } else {
            load_u(ks - (NK - 2));            // ks==6: half0 -> slot2; ks==7: half1 -> slot0
        }

        uint32_t aHi = smBase + s * STAGE_T + warp_m * 4096 + cA;
        uint32_t bHi = smBase + s * STAGE_T + 16384 + warp_n * 2048 + cB;
#pragma unroll
        for (int kh = 0; kh < 2; kh++) {
            uint32_t ah[4][4], al[4][4], bh[2][4], bl[2][4];
            // all fragment loads up-front; latency hidden by 96 mma below
#pragma unroll
            for (int mt = 0; mt < 4; mt++)
                ldsm_x4(ah[mt], aHi + mt * 1024 + kh * 256);
#pragma unroll
            for (int h = 0; h < 2; h++) {
                ldsm_x4(bh[h], bHi + h * 1024 + kh * 256);
                ldsm_x4(bl[h], bHi + 8192 + h * 1024 + kh * 256);
            }
#pragma unroll
            for (int mt = 0; mt < 4; mt++)
                ldsm_x4(al[mt], aHi + 8192 + mt * 1024 + kh * 256);
            // term 1: hi*hi
#pragma unroll
            for (int mt = 0; mt < 4; mt++)
#pragma unroll
                for (int h = 0; h < 2; h++) {
                    mma16816(acc[mt][2 * h],     ah[mt], bh[h][0], bh[h][1]);
                    mma16816(acc[mt][2 * h + 1], ah[mt], bh[h][2], bh[h][3]);
                }
            // term 2: hi*lo
#pragma unroll
            for (int mt = 0; mt < 4; mt++)
#pragma unroll
                for (int h = 0; h < 2; h++) {
                    mma16816(acc[mt][2 * h],     ah[mt], bl[h][0], bl[h][1]);
                    mma16816(acc[mt][2 * h + 1], ah[mt], bl[h][2], bl[h][3]);
                }
            // term 3: lo*hi
#pragma unroll
            for (int mt = 0; mt < 4; mt++)
#pragma unroll
                for (int h = 0; h < 2; h++) {
                    mma16816(acc[mt][2 * h],     al[mt], bh[h][0], bh[h][1]);
                    mma16816(acc[mt][2 * h + 1], al[mt], bh[h][2], bh[h][3]);
                }
        }
    }

    // drain U halves, make smem writes visible to all warps
    asm volatile("cp.async.wait_group 0;");
    __syncthreads();

    // ---- epilogue: packed f32x2 math, U from smem, coalesced v2 stores ----
    float scale = expf(gls[0]);
    float nhs = -0.5f / scale;
    const int rl = lane >> 2, cl = (lane & 3) * 2;
    const uint32_t uB = warp_m ? smBase : (smBase + 2 * STAGE_T);

#pragma unroll
    for (int mt = 0; mt < 4; mt++) {
        int lr = warp_m * 64 + mt * 16 + rl;
        int rloc = mt * 16 + rl;              // local row within half (0..63)
        float na0 = snA[lr], na1 = snA[lr + 8];
        size_t g0 = (size_t)(a0 + lr) * NN + b0;
        size_t g1 = g0 + (size_t)8 * NN;
#pragma unroll
        for (int ng = 0; ng < 4; ng++) {
            int cc = warp_n * 32 + ng * 8 + cl;
            float nb0 = snB[cc], nb1 = snB[cc + 1];
            uint32_t uoff = (uint32_t)((((cc >> 2) ^ rl) << 4) + ((cc & 3) << 2));
            float2 u0 = lds64(uB + rloc * 512 + uoff);
            float2 u1 = lds64(uB + (rloc + 8) * 512 + uoff);
            const float* ac = acc[mt][ng];
            float2 o0 = epi2(ac[0], ac[1], na0, nb0, nb1, nhs, u0.x, u0.y);
            float2 o1 = epi2(ac[2], ac[3], na1, nb0, nb1, nhs, u1.x, u1.y);
            *(float2*)&Out[g0 + cc] = o0;      // lower-tri garbage in tri tiles
            *(float2*)&Out[g1 + cc] = o1;      // is never read by k_permG
        }
    }
}

// ---------------- K4: permute G back (float4, half-row read) -------------
__global__ void k_permG(float* __restrict__ out0) {
    __shared__ float rowbuf[NN];
    int i = blockIdx.x;
    int a = d_rank[i];
    const float4* src = (const float4*)(d_Gs + (size_t)a * NN);
    // only columns > a of sorted row a are ever read (rj > a below)
    int j4start = a >> 2;
    for (int j = j4start + threadIdx.x; j < NN / 4; j += blockDim.x)
        ((float4*)rowbuf)[j] = src[j];
    __syncthreads();
    float4* dst = (float4*)(out0 + (size_t)i * NN);
    const int4* rk = (const int4*)d_rank;
    for (int j4 = threadIdx.x; j4 < NN / 4; j4 += blockDim.x) {
        int4 rj = rk[j4];
        float4 v;
        v.x = (rj.x > a) ? rowbuf[rj.x] : 0.0f;
        v.y = (rj.y > a) ? rowbuf[rj.y] : 0.0f;
        v.z = (rj.z > a) ? rowbuf[rj.z] : 0.0f;
        v.w = (rj.w > a) ? rowbuf[rj.w] : 0.0f;
        dst[j4] = v;
    }
}

// ---------------- launch ---------------------------------------------------
extern "C" void kernel_launch(void* const* d_in, const int* in_sizes, int n_in,
                              void* d_out, int out_size) {
    (void)in_sizes; (void)n_in; (void)out_size;
    const float* uR  = (const float*)d_in[0];
    const float* uM  = (const float*)d_in[1];
    const float* gls = (const float*)d_in[2];
    const float* uG  = (const float*)d_in[3];
    const float* uA  = (const float*)d_in[4];
    float* out = (float*)d_out;

    // opt-in for 96KB dynamic smem (host-side, capture-legal, idempotent)
    cudaFuncSetAttribute(k_gemm, cudaFuncAttributeMaxDynamicSharedMemorySize, SMEM_DYN);

    k_pre<<<2 * NN, 256>>>(uR, uM);   // keys + norms + bf16 splits + rank zeroing
    {
        dim3 g(16, 16);
        k_rankp<<<g, 256>>>();        // parallel partial rank counts
    }
    k_sidx<<<16, 256>>>();

    __nv_bfloat16 *Rhi, *Rlo, *Mhi, *Mlo;
    cudaGetSymbolAddress((void**)&Rhi, d_Rhi);
    cudaGetSymbolAddress((void**)&Rlo, d_Rlo);
    cudaGetSymbolAddress((void**)&Mhi, d_Mhi);
    cudaGetSymbolAddress((void**)&Mlo, d_Mlo);
    float* Gs;
    cudaGetSymbolAddress((void**)&Gs, d_Gs);

    // merged G (528 triangle tiles) + A (1024 tiles) in one launch
    k_gemm<<<1552, 256, SMEM_DYN>>>(Rhi, Rlo, Mhi, Mlo, uG, uA, gls,
                                    Gs, out + (size_t)NN * NN);
    k_permG<<<NN, 512>>>(out);
}